// round 7
// baseline (speedup 1.0000x reference)
#include <cuda_runtime.h>

// Problem constants
#define PP      128                 // polygons
#define NN      128                 // pred points per polygon per level
#define MM      1024                // gt points per polygon
#define CHUNKS  8
#define CM      (MM/CHUNKS)         // 128 gt points per chunk
#define LVL_STRIDE (PP*NN)          // 16384
#define TOTPT   (3*LVL_STRIDE)      // 49152
#define TB      48                  // tail CTAs

// level weights / (3 * P * N)
#define W0 (0.2f/49152.0f)
#define W1 (0.3f/49152.0f)
#define W2 (0.5f/49152.0f)

typedef unsigned long long u64;

// Scratch (no allocations allowed).
// g_min holds key = 0x7F800000 - bits(d^2), so MAX-reduce == min(d^2) and the
// identity element is 0 -> valid zero-init on first run; tail resets to 0.
__device__ unsigned g_min[TOTPT];
__device__ float    g_bsum[TB];
__device__ int      g_cnt2;          // tail ticket (zero-init; tail resets)

// ---- packed f32x2 helpers (sm_103a). fma2 is pure (non-volatile): schedulable. ----
__device__ __forceinline__ u64 pack2(float x) {
    u64 r; asm("mov.b64 %0, {%1, %1};" : "=l"(r) : "f"(x)); return r;
}
__device__ __forceinline__ u64 fma2(u64 a, u64 b, u64 c) {
    u64 d; asm("fma.rn.f32x2 %0, %1, %2, %3;" : "=l"(d) : "l"(a), "l"(b), "l"(c)); return d;
}
__device__ __forceinline__ void min2acc(float& m0, float& m1, u64 t) {
    float2 f = *reinterpret_cast<float2*>(&t);
    m0 = fminf(m0, f.x);
    m1 = fminf(m1, f.y);
}
// Encode non-negative d^2 so that unsigned-max == float-min, identity = 0.
__device__ __forceinline__ unsigned enc_d2(float d2) {
    return 0x7F800000u - __float_as_uint(fmaxf(d2, 0.0f));
}

// Hot kernel: grid (CHUNKS, PP), 64 threads; each thread owns 2 points x 3 levels.
// No fences, no intermediate tensor: min lands in L2 via REDG.MAX on encoded keys.
__global__ __launch_bounds__(64) void k_partial(
    const float* __restrict__ pred0, const float* __restrict__ pred1,
    const float* __restrict__ pred2, const float* __restrict__ gt)
{
    __shared__ __align__(16) float sA[CM];
    __shared__ __align__(16) float sB[CM];
    __shared__ __align__(16) float sC[CM];

    const int ch  = blockIdx.x;
    const int p   = blockIdx.y;
    const int tid = threadIdx.x;

    // Load gt chunk, precompute A=-2gx, B=-2gy, C=|g|^2  (128 pts by 64 threads)
    {
        const float2* gsrc = (const float2*)(gt + ((size_t)p * MM + (size_t)ch * CM) * 2);
        #pragma unroll
        for (int k = 0; k < 2; k++) {
            int m = tid + k * 64;
            float2 g = gsrc[m];
            sA[m] = -2.0f * g.x;
            sB[m] = -2.0f * g.y;
            sC[m] = fmaf(g.x, g.x, g.y * g.y);
        }
    }

    // Two points per thread, 3 levels each; coords are [...,1:] of last dim 3
    const int n0 = 2 * tid, n1 = 2 * tid + 1;
    const int ba = (p * NN + n0) * 3;
    const int bb = (p * NN + n1) * 3;
    const float x0a = pred0[ba + 1], y0a = pred0[ba + 2];
    const float x1a = pred1[ba + 1], y1a = pred1[ba + 2];
    const float x2a = pred2[ba + 1], y2a = pred2[ba + 2];
    const float x0b = pred0[bb + 1], y0b = pred0[bb + 2];
    const float x1b = pred1[bb + 1], y1b = pred1[bb + 2];
    const float x2b = pred2[bb + 1], y2b = pred2[bb + 2];
    __syncthreads();

    const u64 X0a = pack2(x0a), Y0a = pack2(y0a), X0b = pack2(x0b), Y0b = pack2(y0b);
    const u64 X1a = pack2(x1a), Y1a = pack2(y1a), X1b = pack2(x1b), Y1b = pack2(y1b);
    const u64 X2a = pack2(x2a), Y2a = pack2(y2a), X2b = pack2(x2b), Y2b = pack2(y2b);

    const float INF = __int_as_float(0x7f800000);
    float m0a0 = INF, m0a1 = INF, m0b0 = INF, m0b1 = INF;
    float m1a0 = INF, m1a1 = INF, m1b0 = INF, m1b1 = INF;
    float m2a0 = INF, m2a1 = INF, m2b0 = INF, m2b1 = INF;

    const ulonglong2* A2 = (const ulonglong2*)sA;   // plain derefs -> schedulable LDS.128
    const ulonglong2* B2 = (const ulonglong2*)sB;
    const ulonglong2* C2 = (const ulonglong2*)sC;

    #pragma unroll 8
    for (int i = 0; i < CM / 4; i++) {              // 4 gt points per iteration
        ulonglong2 av = A2[i], bv = B2[i], cv = C2[i];
        // level 0
        min2acc(m0a0, m0a1, fma2(Y0a, bv.x, fma2(X0a, av.x, cv.x)));
        min2acc(m0a0, m0a1, fma2(Y0a, bv.y, fma2(X0a, av.y, cv.y)));
        min2acc(m0b0, m0b1, fma2(Y0b, bv.x, fma2(X0b, av.x, cv.x)));
        min2acc(m0b0, m0b1, fma2(Y0b, bv.y, fma2(X0b, av.y, cv.y)));
        // level 1
        min2acc(m1a0, m1a1, fma2(Y1a, bv.x, fma2(X1a, av.x, cv.x)));
        min2acc(m1a0, m1a1, fma2(Y1a, bv.y, fma2(X1a, av.y, cv.y)));
        min2acc(m1b0, m1b1, fma2(Y1b, bv.x, fma2(X1b, av.x, cv.x)));
        min2acc(m1b0, m1b1, fma2(Y1b, bv.y, fma2(X1b, av.y, cv.y)));
        // level 2
        min2acc(m2a0, m2a1, fma2(Y2a, bv.x, fma2(X2a, av.x, cv.x)));
        min2acc(m2a0, m2a1, fma2(Y2a, bv.y, fma2(X2a, av.y, cv.y)));
        min2acc(m2b0, m2b1, fma2(Y2b, bv.x, fma2(X2b, av.x, cv.x)));
        min2acc(m2b0, m2b1, fma2(Y2b, bv.y, fma2(X2b, av.y, cv.y)));
    }

    const int pta = p * NN + n0;
    const int ptb = p * NN + n1;
    atomicMax(&g_min[0 * LVL_STRIDE + pta], enc_d2(fminf(m0a0, m0a1) + fmaf(x0a, x0a, y0a * y0a)));
    atomicMax(&g_min[0 * LVL_STRIDE + ptb], enc_d2(fminf(m0b0, m0b1) + fmaf(x0b, x0b, y0b * y0b)));
    atomicMax(&g_min[1 * LVL_STRIDE + pta], enc_d2(fminf(m1a0, m1a1) + fmaf(x1a, x1a, y1a * y1a)));
    atomicMax(&g_min[1 * LVL_STRIDE + ptb], enc_d2(fminf(m1b0, m1b1) + fmaf(x1b, x1b, y1b * y1b)));
    atomicMax(&g_min[2 * LVL_STRIDE + pta], enc_d2(fminf(m2a0, m2a1) + fmaf(x2a, x2a, y2a * y2a)));
    atomicMax(&g_min[2 * LVL_STRIDE + ptb], enc_d2(fminf(m2b0, m2b1) + fmaf(x2b, x2b, y2b * y2b)));
}

// Tail: 48 CTAs x 256 threads; each thread decodes one uint4 (4 points, same level),
// resets g_min to 0 for the next replay, block-reduces, ticket, final CTA sums 48.
__global__ __launch_bounds__(256) void k_tail(float* __restrict__ out)
{
    __shared__ float s_red[256];
    __shared__ int s_final;

    const int tid = threadIdx.x;
    const int t   = blockIdx.x * 256 + tid;         // uint4 index, 12288 total

    uint4* gp = reinterpret_cast<uint4*>(g_min) + t;
    uint4 k = *gp;                                   // LDG.128 (L2 resident)
    *gp = make_uint4(0, 0, 0, 0);                    // reset for next graph replay

    const int j = t * 4;                             // element index
    const int level = j >> 14;                       // 4 | 16384 -> uniform per thread
    const float w = (level == 0) ? W0 : ((level == 1) ? W1 : W2);

    float s;
    {
        float d0 = sqrtf(__uint_as_float(0x7F800000u - k.x));
        float d1 = sqrtf(__uint_as_float(0x7F800000u - k.y));
        float d2 = sqrtf(__uint_as_float(0x7F800000u - k.z));
        float d3 = sqrtf(__uint_as_float(0x7F800000u - k.w));
        s = w * ((d0 + d1) + (d2 + d3));
    }
    s_red[tid] = s;
    __syncthreads();
    #pragma unroll
    for (int off = 128; off > 0; off >>= 1) {
        if (tid < off) s_red[tid] += s_red[tid + off];
        __syncthreads();
    }

    if (tid == 0) {
        g_bsum[blockIdx.x] = s_red[0];
        __threadfence();                             // release g_bsum
        int t2 = atomicAdd(&g_cnt2, 1);
        s_final = (t2 == TB - 1);
        if (s_final) g_cnt2 = 0;                     // reset for next graph replay
    }
    __syncthreads();
    if (!s_final) return;

    __threadfence();                                 // acquire other CTAs' g_bsum
    s_red[tid] = (tid < TB) ? __ldcg(&g_bsum[tid]) : 0.0f;
    __syncthreads();
    #pragma unroll
    for (int off = 128; off > 0; off >>= 1) {
        if (tid < off) s_red[tid] += s_red[tid + off];
        __syncthreads();
    }
    if (tid == 0) *out = s_red[0];
}

extern "C" void kernel_launch(void* const* d_in, const int* in_sizes, int n_in,
                              void* d_out, int out_size)
{
    const float* pred0 = (const float*)d_in[0];
    const float* pred1 = (const float*)d_in[1];
    const float* pred2 = (const float*)d_in[2];
    const float* gt    = (const float*)d_in[3];

    dim3 grid(CHUNKS, PP);
    k_partial<<<grid, 64>>>(pred0, pred1, pred2, gt);
    k_tail<<<TB, 256>>>((float*)d_out);
}

// round 8
// speedup vs baseline: 1.0657x; 1.0657x over previous
#include <cuda_runtime.h>

// Problem constants
#define PP      128                 // polygons
#define NN      128                 // pred points per polygon per level
#define MM      1024                // gt points per polygon
#define CHUNKS  8
#define CM      (MM/CHUNKS)         // 128 gt points per chunk
#define LVL_STRIDE (PP*NN)          // 16384
#define TOTPT   (3*LVL_STRIDE)      // 49152
#define TB      48                  // tail CTAs (48*256*4 = 49152 points)

// level weights / (3 * P * N)
#define W0 (0.2f/49152.0f)
#define W1 (0.3f/49152.0f)
#define W2 (0.5f/49152.0f)

typedef unsigned long long u64;

// Scratch (no allocations allowed)
__device__ float g_partial[CHUNKS][TOTPT];   // min d^2 per (chunk, level*point)
__device__ float g_bsum[TB];
__device__ int   g_cnt2;                     // tail ticket (zero-init; tail resets)

// ---- packed f32x2 helpers (sm_103a). fma2 is pure (non-volatile): schedulable. ----
__device__ __forceinline__ u64 pack2(float x) {
    u64 r; asm("mov.b64 %0, {%1, %1};" : "=l"(r) : "f"(x)); return r;
}
__device__ __forceinline__ u64 fma2(u64 a, u64 b, u64 c) {
    u64 d; asm("fma.rn.f32x2 %0, %1, %2, %3;" : "=l"(d) : "l"(a), "l"(b), "l"(c)); return d;
}
__device__ __forceinline__ void min2acc(float& m0, float& m1, u64 t) {
    float2 f = *reinterpret_cast<float2*>(&t);
    m0 = fminf(m0, f.x);
    m1 = fminf(m1, f.y);
}

// Hot kernel (identical to R6 best): grid (CHUNKS, PP), 64 threads;
// each thread owns 2 points x 3 levels. No fences, no atomics.
__global__ __launch_bounds__(64) void k_partial(
    const float* __restrict__ pred0, const float* __restrict__ pred1,
    const float* __restrict__ pred2, const float* __restrict__ gt)
{
    __shared__ __align__(16) float sA[CM];
    __shared__ __align__(16) float sB[CM];
    __shared__ __align__(16) float sC[CM];

    const int ch  = blockIdx.x;
    const int p   = blockIdx.y;
    const int tid = threadIdx.x;

    // Load gt chunk, precompute A=-2gx, B=-2gy, C=|g|^2  (128 pts by 64 threads)
    {
        const float2* gsrc = (const float2*)(gt + ((size_t)p * MM + (size_t)ch * CM) * 2);
        #pragma unroll
        for (int k = 0; k < 2; k++) {
            int m = tid + k * 64;
            float2 g = gsrc[m];
            sA[m] = -2.0f * g.x;
            sB[m] = -2.0f * g.y;
            sC[m] = fmaf(g.x, g.x, g.y * g.y);
        }
    }

    // Two points per thread, 3 levels each; coords are [...,1:] of last dim 3
    const int n0 = 2 * tid, n1 = 2 * tid + 1;
    const int ba = (p * NN + n0) * 3;
    const int bb = (p * NN + n1) * 3;
    const float x0a = pred0[ba + 1], y0a = pred0[ba + 2];
    const float x1a = pred1[ba + 1], y1a = pred1[ba + 2];
    const float x2a = pred2[ba + 1], y2a = pred2[ba + 2];
    const float x0b = pred0[bb + 1], y0b = pred0[bb + 2];
    const float x1b = pred1[bb + 1], y1b = pred1[bb + 2];
    const float x2b = pred2[bb + 1], y2b = pred2[bb + 2];
    __syncthreads();

    const u64 X0a = pack2(x0a), Y0a = pack2(y0a), X0b = pack2(x0b), Y0b = pack2(y0b);
    const u64 X1a = pack2(x1a), Y1a = pack2(y1a), X1b = pack2(x1b), Y1b = pack2(y1b);
    const u64 X2a = pack2(x2a), Y2a = pack2(y2a), X2b = pack2(x2b), Y2b = pack2(y2b);

    const float INF = __int_as_float(0x7f800000);
    float m0a0 = INF, m0a1 = INF, m0b0 = INF, m0b1 = INF;
    float m1a0 = INF, m1a1 = INF, m1b0 = INF, m1b1 = INF;
    float m2a0 = INF, m2a1 = INF, m2b0 = INF, m2b1 = INF;

    const ulonglong2* A2 = (const ulonglong2*)sA;   // plain derefs -> schedulable LDS.128
    const ulonglong2* B2 = (const ulonglong2*)sB;
    const ulonglong2* C2 = (const ulonglong2*)sC;

    #pragma unroll 8
    for (int i = 0; i < CM / 4; i++) {              // 4 gt points per iteration
        ulonglong2 av = A2[i], bv = B2[i], cv = C2[i];
        // level 0
        min2acc(m0a0, m0a1, fma2(Y0a, bv.x, fma2(X0a, av.x, cv.x)));
        min2acc(m0a0, m0a1, fma2(Y0a, bv.y, fma2(X0a, av.y, cv.y)));
        min2acc(m0b0, m0b1, fma2(Y0b, bv.x, fma2(X0b, av.x, cv.x)));
        min2acc(m0b0, m0b1, fma2(Y0b, bv.y, fma2(X0b, av.y, cv.y)));
        // level 1
        min2acc(m1a0, m1a1, fma2(Y1a, bv.x, fma2(X1a, av.x, cv.x)));
        min2acc(m1a0, m1a1, fma2(Y1a, bv.y, fma2(X1a, av.y, cv.y)));
        min2acc(m1b0, m1b1, fma2(Y1b, bv.x, fma2(X1b, av.x, cv.x)));
        min2acc(m1b0, m1b1, fma2(Y1b, bv.y, fma2(X1b, av.y, cv.y)));
        // level 2
        min2acc(m2a0, m2a1, fma2(Y2a, bv.x, fma2(X2a, av.x, cv.x)));
        min2acc(m2a0, m2a1, fma2(Y2a, bv.y, fma2(X2a, av.y, cv.y)));
        min2acc(m2b0, m2b1, fma2(Y2b, bv.x, fma2(X2b, av.x, cv.x)));
        min2acc(m2b0, m2b1, fma2(Y2b, bv.y, fma2(X2b, av.y, cv.y)));
    }

    const int pta = p * NN + n0;
    const int ptb = p * NN + n1;
    g_partial[ch][0 * LVL_STRIDE + pta] = fminf(m0a0, m0a1) + fmaf(x0a, x0a, y0a * y0a);
    g_partial[ch][0 * LVL_STRIDE + ptb] = fminf(m0b0, m0b1) + fmaf(x0b, x0b, y0b * y0b);
    g_partial[ch][1 * LVL_STRIDE + pta] = fminf(m1a0, m1a1) + fmaf(x1a, x1a, y1a * y1a);
    g_partial[ch][1 * LVL_STRIDE + ptb] = fminf(m1b0, m1b1) + fmaf(x1b, x1b, y1b * y1b);
    g_partial[ch][2 * LVL_STRIDE + pta] = fminf(m2a0, m2a1) + fmaf(x2a, x2a, y2a * y2a);
    g_partial[ch][2 * LVL_STRIDE + ptb] = fminf(m2b0, m2b1) + fmaf(x2b, x2b, y2b * y2b);
}

// Tail v2: 48 CTAs x 256 threads. Each thread: 8 INDEPENDENT float4 loads
// (one per chunk, all in flight) -> componentwise min -> 4 sqrts -> weighted sum.
__global__ __launch_bounds__(256) void k_tail(float* __restrict__ out)
{
    __shared__ float s_red[256];
    __shared__ int s_final;

    const int tid = threadIdx.x;
    const int t   = blockIdx.x * 256 + tid;         // float4 index, 12288 total

    // 8 independent LDG.128 — MLP=8, one latency quantum
    float4 v[CHUNKS];
    #pragma unroll
    for (int c = 0; c < CHUNKS; c++)
        v[c] = reinterpret_cast<const float4*>(g_partial[c])[t];

    float4 m = v[0];
    #pragma unroll
    for (int c = 1; c < CHUNKS; c++) {
        m.x = fminf(m.x, v[c].x);
        m.y = fminf(m.y, v[c].y);
        m.z = fminf(m.z, v[c].z);
        m.w = fminf(m.w, v[c].w);
    }

    const int level = t >> 12;                      // (t*4) >> 14
    const float w = (level == 0) ? W0 : ((level == 1) ? W1 : W2);
    float s = w * ((sqrtf(fmaxf(m.x, 0.0f)) + sqrtf(fmaxf(m.y, 0.0f))) +
                   (sqrtf(fmaxf(m.z, 0.0f)) + sqrtf(fmaxf(m.w, 0.0f))));

    s_red[tid] = s;
    __syncthreads();
    #pragma unroll
    for (int off = 128; off > 0; off >>= 1) {
        if (tid < off) s_red[tid] += s_red[tid + off];
        __syncthreads();
    }

    if (tid == 0) {
        g_bsum[blockIdx.x] = s_red[0];
        __threadfence();                             // release g_bsum
        int t2 = atomicAdd(&g_cnt2, 1);
        s_final = (t2 == TB - 1);
        if (s_final) g_cnt2 = 0;                     // reset for next graph replay
    }
    __syncthreads();
    if (!s_final) return;

    __threadfence();                                 // acquire other CTAs' g_bsum
    s_red[tid] = (tid < TB) ? __ldcg(&g_bsum[tid]) : 0.0f;
    __syncthreads();
    #pragma unroll
    for (int off = 128; off > 0; off >>= 1) {
        if (tid < off) s_red[tid] += s_red[tid + off];
        __syncthreads();
    }
    if (tid == 0) *out = s_red[0];
}

extern "C" void kernel_launch(void* const* d_in, const int* in_sizes, int n_in,
                              void* d_out, int out_size)
{
    const float* pred0 = (const float*)d_in[0];
    const float* pred1 = (const float*)d_in[1];
    const float* pred2 = (const float*)d_in[2];
    const float* gt    = (const float*)d_in[3];

    dim3 grid(CHUNKS, PP);
    k_partial<<<grid, 64>>>(pred0, pred1, pred2, gt);
    k_tail<<<TB, 256>>>((float*)d_out);
}

// round 9
// speedup vs baseline: 1.2298x; 1.1540x over previous
#include <cuda_runtime.h>

// Problem constants
#define PP      128                 // polygons
#define NN      128                 // pred points per polygon per level
#define MM      1024                // gt points per polygon
#define H       4                   // gt quarters per polygon
#define GPH     (MM/H)              // 256 gt per quarter
#define THREADS 512                 // = NN * H

// level weights / (3 * P * N)
#define W0 (0.2f/49152.0f)
#define W1 (0.3f/49152.0f)
#define W2 (0.5f/49152.0f)

typedef unsigned long long u64;

// Scratch (no allocations allowed)
__device__ float g_poly[PP];        // per-polygon weighted sums
__device__ int   g_cnt2;            // ticket (zero-init; winner resets)

// ---- packed f32x2 helpers (sm_103a). fma2 is pure (non-volatile): schedulable. ----
__device__ __forceinline__ u64 pack2(float x) {
    u64 r; asm("mov.b64 %0, {%1, %1};" : "=l"(r) : "f"(x)); return r;
}
__device__ __forceinline__ u64 fma2(u64 a, u64 b, u64 c) {
    u64 d; asm("fma.rn.f32x2 %0, %1, %2, %3;" : "=l"(d) : "l"(a), "l"(b), "l"(c)); return d;
}
__device__ __forceinline__ void min2acc(float& m0, float& m1, u64 t) {
    float2 f = *reinterpret_cast<float2*>(&t);
    m0 = fminf(m0, f.x);
    m1 = fminf(m1, f.y);
}

// Single kernel: CTA = polygon. 512 threads = 128 points x 4 gt-quarters.
__global__ __launch_bounds__(THREADS) void k_all(
    const float* __restrict__ pred0, const float* __restrict__ pred1,
    const float* __restrict__ pred2, const float* __restrict__ gt,
    float* __restrict__ out)
{
    __shared__ __align__(16) float sA[MM];
    __shared__ __align__(16) float sB[MM];
    __shared__ __align__(16) float sC[MM];
    __shared__ float s_half[3 * H * NN];   // [level][quarter][point]
    __shared__ float s_warp[16];
    __shared__ int   s_final;

    const int p = blockIdx.x;
    const int t = threadIdx.x;

    // ---- load ALL gt of this polygon; precompute A=-2gx, B=-2gy, C=|g|^2 ----
    {
        const float2* gsrc = (const float2*)(gt + (size_t)p * MM * 2);
        #pragma unroll
        for (int k = 0; k < 2; k++) {
            int m = t + k * THREADS;
            float2 g = gsrc[m];
            sA[m] = -2.0f * g.x;
            sB[m] = -2.0f * g.y;
            sC[m] = fmaf(g.x, g.x, g.y * g.y);
        }
    }

    const int n = t & (NN - 1);            // point index
    const int h = t >> 7;                  // gt quarter
    const int base = (p * NN + n) * 3;     // coords are [...,1:] of last dim 3
    const float x0 = pred0[base + 1], y0 = pred0[base + 2];
    const float x1 = pred1[base + 1], y1 = pred1[base + 2];
    const float x2 = pred2[base + 1], y2 = pred2[base + 2];
    __syncthreads();

    const u64 X0 = pack2(x0), Y0 = pack2(y0);
    const u64 X1 = pack2(x1), Y1 = pack2(y1);
    const u64 X2 = pack2(x2), Y2 = pack2(y2);

    const float INF = __int_as_float(0x7f800000);
    float m00 = INF, m01 = INF, m10 = INF, m11 = INF, m20 = INF, m21 = INF;

    const ulonglong2* A2 = (const ulonglong2*)(sA + h * GPH);  // schedulable LDS.128
    const ulonglong2* B2 = (const ulonglong2*)(sB + h * GPH);
    const ulonglong2* C2 = (const ulonglong2*)(sC + h * GPH);

    #pragma unroll 8
    for (int i = 0; i < GPH / 4; i++) {    // 4 gt points per iteration, 64 iters
        ulonglong2 av = A2[i], bv = B2[i], cv = C2[i];
        min2acc(m00, m01, fma2(Y0, bv.x, fma2(X0, av.x, cv.x)));
        min2acc(m00, m01, fma2(Y0, bv.y, fma2(X0, av.y, cv.y)));
        min2acc(m10, m11, fma2(Y1, bv.x, fma2(X1, av.x, cv.x)));
        min2acc(m10, m11, fma2(Y1, bv.y, fma2(X1, av.y, cv.y)));
        min2acc(m20, m21, fma2(Y2, bv.x, fma2(X2, av.x, cv.x)));
        min2acc(m20, m21, fma2(Y2, bv.y, fma2(X2, av.y, cv.y)));
    }

    // per-(level, quarter, point) partial min d^2
    s_half[(0 * H + h) * NN + n] = fminf(m00, m01) + fmaf(x0, x0, y0 * y0);
    s_half[(1 * H + h) * NN + n] = fminf(m10, m11) + fmaf(x1, x1, y1 * y1);
    s_half[(2 * H + h) * NN + n] = fminf(m20, m21) + fmaf(x2, x2, y2 * y2);
    __syncthreads();

    // ---- combine quarters: threads 0..383 own (level l = t>>7, point n) ----
    float val = 0.0f;
    if (t < 3 * NN) {
        const int l = t >> 7;
        const int nn = t & (NN - 1);
        const float* sh = s_half + l * H * NN + nn;
        float v = fminf(fminf(sh[0 * NN], sh[1 * NN]),
                        fminf(sh[2 * NN], sh[3 * NN]));
        const float w = (l == 0) ? W0 : ((l == 1) ? W1 : W2);
        val = w * sqrtf(fmaxf(v, 0.0f));
    }
    // deterministic fixed-tree reduction: shfl butterfly + fixed-order warp sums
    #pragma unroll
    for (int off = 16; off > 0; off >>= 1)
        val += __shfl_xor_sync(0xffffffffu, val, off);
    if ((t & 31) == 0) s_warp[t >> 5] = val;
    __syncthreads();

    if (t == 0) {
        float s = 0.0f;
        #pragma unroll
        for (int i = 0; i < 16; i++) s += s_warp[i];
        g_poly[p] = s;
        __threadfence();                   // release g_poly[p]
        int tk = atomicAdd(&g_cnt2, 1);
        s_final = (tk == PP - 1);
        if (s_final) g_cnt2 = 0;           // reset for next graph replay
    }
    __syncthreads();
    if (!s_final) return;                  // uniform across CTA

    // ---- last CTA: sum the 128 polygon scalars (fixed order) ----
    __threadfence();                       // acquire other CTAs' g_poly writes
    float v2 = (t < PP) ? __ldcg(&g_poly[t]) : 0.0f;
    #pragma unroll
    for (int off = 16; off > 0; off >>= 1)
        v2 += __shfl_xor_sync(0xffffffffu, v2, off);
    if ((t & 31) == 0) s_warp[t >> 5] = v2;
    __syncthreads();
    if (t == 0) {
        float s = 0.0f;
        #pragma unroll
        for (int i = 0; i < 16; i++) s += s_warp[i];   // warps >=4 contribute 0
        *out = s;
    }
}

extern "C" void kernel_launch(void* const* d_in, const int* in_sizes, int n_in,
                              void* d_out, int out_size)
{
    const float* pred0 = (const float*)d_in[0];
    const float* pred1 = (const float*)d_in[1];
    const float* pred2 = (const float*)d_in[2];
    const float* gt    = (const float*)d_in[3];

    k_all<<<PP, THREADS>>>(pred0, pred1, pred2, gt, (float*)d_out);
}

// round 10
// speedup vs baseline: 1.2359x; 1.0049x over previous
#include <cuda_runtime.h>

// Problem constants
#define PP      128                 // polygons
#define NN      128                 // pred points per polygon per level
#define MM      1024                // gt points per polygon
#define H       8                   // gt slices per polygon
#define GPH     (MM/H)              // 128 gt per slice
#define THREADS 1024                // = NN * H

// level weights / (3 * P * N)
#define W0 (0.2f/49152.0f)
#define W1 (0.3f/49152.0f)
#define W2 (0.5f/49152.0f)

typedef unsigned long long u64;

// Scratch (no allocations allowed)
__device__ float g_poly[PP];        // per-polygon weighted sums
__device__ int   g_cnt2;            // ticket (zero-init; winner resets)

// ---- packed f32x2 helpers (sm_103a). fma2 is pure (non-volatile): schedulable. ----
__device__ __forceinline__ u64 pack2(float x) {
    u64 r; asm("mov.b64 %0, {%1, %1};" : "=l"(r) : "f"(x)); return r;
}
__device__ __forceinline__ u64 fma2(u64 a, u64 b, u64 c) {
    u64 d; asm("fma.rn.f32x2 %0, %1, %2, %3;" : "=l"(d) : "l"(a), "l"(b), "l"(c)); return d;
}
__device__ __forceinline__ void min2acc(float& m0, float& m1, u64 t) {
    float2 f = *reinterpret_cast<float2*>(&t);
    m0 = fminf(m0, f.x);
    m1 = fminf(m1, f.y);
}

// Single kernel: CTA = polygon. 1024 threads = 128 points x 8 gt-slices.
__global__ __launch_bounds__(THREADS) void k_all(
    const float* __restrict__ pred0, const float* __restrict__ pred1,
    const float* __restrict__ pred2, const float* __restrict__ gt,
    float* __restrict__ out)
{
    __shared__ __align__(16) float sA[MM];
    __shared__ __align__(16) float sB[MM];
    __shared__ __align__(16) float sC[MM];
    __shared__ float s_half[3 * H * NN];   // [level][slice][point]
    __shared__ float s_warp[32];
    __shared__ int   s_final;

    const int p = blockIdx.x;
    const int t = threadIdx.x;

    // ---- load ALL gt of this polygon; precompute A=-2gx, B=-2gy, C=|g|^2 ----
    {
        const float2* gsrc = (const float2*)(gt + (size_t)p * MM * 2);
        float2 g = gsrc[t];
        sA[t] = -2.0f * g.x;
        sB[t] = -2.0f * g.y;
        sC[t] = fmaf(g.x, g.x, g.y * g.y);
    }

    const int n = t & (NN - 1);            // point index
    const int h = t >> 7;                  // gt slice
    const int base = (p * NN + n) * 3;     // coords are [...,1:] of last dim 3
    const float x0 = pred0[base + 1], y0 = pred0[base + 2];
    const float x1 = pred1[base + 1], y1 = pred1[base + 2];
    const float x2 = pred2[base + 1], y2 = pred2[base + 2];
    __syncthreads();

    const u64 X0 = pack2(x0), Y0 = pack2(y0);
    const u64 X1 = pack2(x1), Y1 = pack2(y1);
    const u64 X2 = pack2(x2), Y2 = pack2(y2);

    const float INF = __int_as_float(0x7f800000);
    float m00 = INF, m01 = INF, m10 = INF, m11 = INF, m20 = INF, m21 = INF;

    const ulonglong2* A2 = (const ulonglong2*)(sA + h * GPH);  // schedulable LDS.128
    const ulonglong2* B2 = (const ulonglong2*)(sB + h * GPH);
    const ulonglong2* C2 = (const ulonglong2*)(sC + h * GPH);

    #pragma unroll 4
    for (int i = 0; i < GPH / 4; i++) {    // 4 gt points per iteration, 32 iters
        ulonglong2 av = A2[i], bv = B2[i], cv = C2[i];
        min2acc(m00, m01, fma2(Y0, bv.x, fma2(X0, av.x, cv.x)));
        min2acc(m00, m01, fma2(Y0, bv.y, fma2(X0, av.y, cv.y)));
        min2acc(m10, m11, fma2(Y1, bv.x, fma2(X1, av.x, cv.x)));
        min2acc(m10, m11, fma2(Y1, bv.y, fma2(X1, av.y, cv.y)));
        min2acc(m20, m21, fma2(Y2, bv.x, fma2(X2, av.x, cv.x)));
        min2acc(m20, m21, fma2(Y2, bv.y, fma2(X2, av.y, cv.y)));
    }

    // per-(level, slice, point) partial min d^2
    s_half[(0 * H + h) * NN + n] = fminf(m00, m01) + fmaf(x0, x0, y0 * y0);
    s_half[(1 * H + h) * NN + n] = fminf(m10, m11) + fmaf(x1, x1, y1 * y1);
    s_half[(2 * H + h) * NN + n] = fminf(m20, m21) + fmaf(x2, x2, y2 * y2);
    __syncthreads();

    // ---- combine slices: threads 0..383 own (level l = t>>7, point n) ----
    float val = 0.0f;
    if (t < 3 * NN) {
        const int l = t >> 7;
        const int nn = t & (NN - 1);
        const float* sh = s_half + l * H * NN + nn;
        float v = fminf(fminf(fminf(sh[0 * NN], sh[1 * NN]),
                              fminf(sh[2 * NN], sh[3 * NN])),
                        fminf(fminf(sh[4 * NN], sh[5 * NN]),
                              fminf(sh[6 * NN], sh[7 * NN])));
        const float w = (l == 0) ? W0 : ((l == 1) ? W1 : W2);
        val = w * sqrtf(fmaxf(v, 0.0f));
    }
    // deterministic fixed-tree reduction: shfl butterfly + fixed-order warp sums
    #pragma unroll
    for (int off = 16; off > 0; off >>= 1)
        val += __shfl_xor_sync(0xffffffffu, val, off);
    if ((t & 31) == 0) s_warp[t >> 5] = val;
    __syncthreads();

    if (t == 0) {
        float s = 0.0f;
        #pragma unroll
        for (int i = 0; i < 12; i++) s += s_warp[i];   // warps >=12 contribute 0
        g_poly[p] = s;
        __threadfence();                   // release g_poly[p]
        int tk = atomicAdd(&g_cnt2, 1);
        s_final = (tk == PP - 1);
        if (s_final) g_cnt2 = 0;           // reset for next graph replay
    }
    __syncthreads();
    if (!s_final) return;                  // uniform across CTA

    // ---- last CTA: sum the 128 polygon scalars (fixed order) ----
    __threadfence();                       // acquire other CTAs' g_poly writes
    float v2 = (t < PP) ? __ldcg(&g_poly[t]) : 0.0f;
    #pragma unroll
    for (int off = 16; off > 0; off >>= 1)
        v2 += __shfl_xor_sync(0xffffffffu, v2, off);
    if ((t & 31) == 0) s_warp[t >> 5] = v2;
    __syncthreads();
    if (t == 0) {
        float s = 0.0f;
        #pragma unroll
        for (int i = 0; i < 4; i++) s += s_warp[i];    // only first 4 warps held data
        *out = s;
    }
}

extern "C" void kernel_launch(void* const* d_in, const int* in_sizes, int n_in,
                              void* d_out, int out_size)
{
    const float* pred0 = (const float*)d_in[0];
    const float* pred1 = (const float*)d_in[1];
    const float* pred2 = (const float*)d_in[2];
    const float* gt    = (const float*)d_in[3];

    k_all<<<PP, THREADS>>>(pred0, pred1, pred2, gt, (float*)d_out);
}

// round 11
// speedup vs baseline: 1.2607x; 1.0201x over previous
#include <cuda_runtime.h>

// Problem constants
#define PP      128                 // polygons
#define NN      128                 // pred points per polygon per level
#define MM      1024                // gt points per polygon
#define H       8                   // gt slices per polygon
#define GPH     (MM/H)              // 128 gt per slice
#define THREADS 512                 // = (NN/2) * H

// level weights / (3 * P * N)
#define W0 (0.2f/49152.0f)
#define W1 (0.3f/49152.0f)
#define W2 (0.5f/49152.0f)

typedef unsigned long long u64;

// Scratch (no allocations allowed)
__device__ float g_poly[PP];        // per-polygon weighted sums
__device__ int   g_cnt2;            // ticket (zero-init; winner resets)

// ---- packed f32x2 helpers (sm_103a). fma2 is pure (non-volatile): schedulable. ----
__device__ __forceinline__ u64 pack2(float x) {
    u64 r; asm("mov.b64 %0, {%1, %1};" : "=l"(r) : "f"(x)); return r;
}
__device__ __forceinline__ u64 fma2(u64 a, u64 b, u64 c) {
    u64 d; asm("fma.rn.f32x2 %0, %1, %2, %3;" : "=l"(d) : "l"(a), "l"(b), "l"(c)); return d;
}
__device__ __forceinline__ void min2acc(float& m0, float& m1, u64 t) {
    float2 f = *reinterpret_cast<float2*>(&t);
    m0 = fminf(m0, f.x);
    m1 = fminf(m1, f.y);
}

// Single kernel: CTA = polygon. 512 threads = 64 point-pairs x 8 gt-slices.
// Each thread: 2 points x 3 levels over 128 gt  (48 compute instrs per 3-LDS
// group -> self-covers the 29-cyc LDS latency; this was R6's speed secret).
__global__ __launch_bounds__(THREADS) void k_all(
    const float* __restrict__ pred0, const float* __restrict__ pred1,
    const float* __restrict__ pred2, const float* __restrict__ gt,
    float* __restrict__ out)
{
    __shared__ __align__(16) float sA[MM];
    __shared__ __align__(16) float sB[MM];
    __shared__ __align__(16) float sC[MM];
    __shared__ float s_half[3 * H * NN];   // [level][slice][point]
    __shared__ float s_warp[16];
    __shared__ int   s_final;

    const int p = blockIdx.x;
    const int t = threadIdx.x;

    const int tn = t & 63;                 // point-pair index (points 2tn, 2tn+1)
    const int h  = t >> 6;                 // gt slice 0..7
    const int n0 = 2 * tn, n1 = 2 * tn + 1;

    // prologue global loads first (overlap with smem fill)
    const int ba = (p * NN + n0) * 3;      // coords are [...,1:] of last dim 3
    const float x0a = pred0[ba + 1], y0a = pred0[ba + 2];
    const float x0b = pred0[ba + 4], y0b = pred0[ba + 5];
    const float x1a = pred1[ba + 1], y1a = pred1[ba + 2];
    const float x1b = pred1[ba + 4], y1b = pred1[ba + 5];
    const float x2a = pred2[ba + 1], y2a = pred2[ba + 2];
    const float x2b = pred2[ba + 4], y2b = pred2[ba + 5];

    // ---- load ALL gt of this polygon; precompute A=-2gx, B=-2gy, C=|g|^2 ----
    {
        const float2* gsrc = (const float2*)(gt + (size_t)p * MM * 2);
        #pragma unroll
        for (int k = 0; k < 2; k++) {
            int m = t + k * THREADS;
            float2 g = gsrc[m];
            sA[m] = -2.0f * g.x;
            sB[m] = -2.0f * g.y;
            sC[m] = fmaf(g.x, g.x, g.y * g.y);
        }
    }
    __syncthreads();

    const u64 X0a = pack2(x0a), Y0a = pack2(y0a), X0b = pack2(x0b), Y0b = pack2(y0b);
    const u64 X1a = pack2(x1a), Y1a = pack2(y1a), X1b = pack2(x1b), Y1b = pack2(y1b);
    const u64 X2a = pack2(x2a), Y2a = pack2(y2a), X2b = pack2(x2b), Y2b = pack2(y2b);

    const float INF = __int_as_float(0x7f800000);
    float m0a0 = INF, m0a1 = INF, m0b0 = INF, m0b1 = INF;
    float m1a0 = INF, m1a1 = INF, m1b0 = INF, m1b1 = INF;
    float m2a0 = INF, m2a1 = INF, m2b0 = INF, m2b1 = INF;

    const ulonglong2* A2 = (const ulonglong2*)(sA + h * GPH);  // schedulable LDS.128
    const ulonglong2* B2 = (const ulonglong2*)(sB + h * GPH);
    const ulonglong2* C2 = (const ulonglong2*)(sC + h * GPH);

    #pragma unroll 8
    for (int i = 0; i < GPH / 4; i++) {    // 4 gt per iter, 32 iters, 51 instrs
        ulonglong2 av = A2[i], bv = B2[i], cv = C2[i];
        // level 0, points a & b
        min2acc(m0a0, m0a1, fma2(Y0a, bv.x, fma2(X0a, av.x, cv.x)));
        min2acc(m0a0, m0a1, fma2(Y0a, bv.y, fma2(X0a, av.y, cv.y)));
        min2acc(m0b0, m0b1, fma2(Y0b, bv.x, fma2(X0b, av.x, cv.x)));
        min2acc(m0b0, m0b1, fma2(Y0b, bv.y, fma2(X0b, av.y, cv.y)));
        // level 1
        min2acc(m1a0, m1a1, fma2(Y1a, bv.x, fma2(X1a, av.x, cv.x)));
        min2acc(m1a0, m1a1, fma2(Y1a, bv.y, fma2(X1a, av.y, cv.y)));
        min2acc(m1b0, m1b1, fma2(Y1b, bv.x, fma2(X1b, av.x, cv.x)));
        min2acc(m1b0, m1b1, fma2(Y1b, bv.y, fma2(X1b, av.y, cv.y)));
        // level 2
        min2acc(m2a0, m2a1, fma2(Y2a, bv.x, fma2(X2a, av.x, cv.x)));
        min2acc(m2a0, m2a1, fma2(Y2a, bv.y, fma2(X2a, av.y, cv.y)));
        min2acc(m2b0, m2b1, fma2(Y2b, bv.x, fma2(X2b, av.x, cv.x)));
        min2acc(m2b0, m2b1, fma2(Y2b, bv.y, fma2(X2b, av.y, cv.y)));
    }

    // per-(level, slice, point) partial min d^2
    s_half[(0 * H + h) * NN + n0] = fminf(m0a0, m0a1) + fmaf(x0a, x0a, y0a * y0a);
    s_half[(0 * H + h) * NN + n1] = fminf(m0b0, m0b1) + fmaf(x0b, x0b, y0b * y0b);
    s_half[(1 * H + h) * NN + n0] = fminf(m1a0, m1a1) + fmaf(x1a, x1a, y1a * y1a);
    s_half[(1 * H + h) * NN + n1] = fminf(m1b0, m1b1) + fmaf(x1b, x1b, y1b * y1b);
    s_half[(2 * H + h) * NN + n0] = fminf(m2a0, m2a1) + fmaf(x2a, x2a, y2a * y2a);
    s_half[(2 * H + h) * NN + n1] = fminf(m2b0, m2b1) + fmaf(x2b, x2b, y2b * y2b);
    __syncthreads();

    // ---- combine slices: threads 0..383 own (level l = t>>7, point nn) ----
    float val = 0.0f;
    if (t < 3 * NN) {
        const int l  = t >> 7;
        const int nn = t & (NN - 1);
        const float* sh = s_half + l * H * NN + nn;
        float v = fminf(fminf(fminf(sh[0 * NN], sh[1 * NN]),
                              fminf(sh[2 * NN], sh[3 * NN])),
                        fminf(fminf(sh[4 * NN], sh[5 * NN]),
                              fminf(sh[6 * NN], sh[7 * NN])));
        const float w = (l == 0) ? W0 : ((l == 1) ? W1 : W2);
        val = w * sqrtf(fmaxf(v, 0.0f));
    }
    // deterministic fixed-tree reduction
    #pragma unroll
    for (int off = 16; off > 0; off >>= 1)
        val += __shfl_xor_sync(0xffffffffu, val, off);
    if ((t & 31) == 0) s_warp[t >> 5] = val;
    __syncthreads();

    if (t == 0) {
        float s = 0.0f;
        #pragma unroll
        for (int i = 0; i < 12; i++) s += s_warp[i];   // warps >=12 contribute 0
        g_poly[p] = s;
        __threadfence();                   // release g_poly[p]
        int tk = atomicAdd(&g_cnt2, 1);
        s_final = (tk == PP - 1);
        if (s_final) g_cnt2 = 0;           // reset for next graph replay
    }
    __syncthreads();
    if (!s_final) return;                  // uniform across CTA

    // ---- last CTA: sum the 128 polygon scalars (fixed order) ----
    __threadfence();                       // acquire other CTAs' g_poly writes
    float v2 = (t < PP) ? __ldcg(&g_poly[t]) : 0.0f;
    #pragma unroll
    for (int off = 16; off > 0; off >>= 1)
        v2 += __shfl_xor_sync(0xffffffffu, v2, off);
    if ((t & 31) == 0) s_warp[t >> 5] = v2;
    __syncthreads();
    if (t == 0) {
        float s = 0.0f;
        #pragma unroll
        for (int i = 0; i < 4; i++) s += s_warp[i];    // only first 4 warps held data
        *out = s;
    }
}

extern "C" void kernel_launch(void* const* d_in, const int* in_sizes, int n_in,
                              void* d_out, int out_size)
{
    const float* pred0 = (const float*)d_in[0];
    const float* pred1 = (const float*)d_in[1];
    const float* pred2 = (const float*)d_in[2];
    const float* gt    = (const float*)d_in[3];

    k_all<<<PP, THREADS>>>(pred0, pred1, pred2, gt, (float*)d_out);
}